// round 1
// baseline (speedup 1.0000x reference)
#include <cuda_runtime.h>
#include <math.h>

// Problem constants (fixed by the reference: N=4096, D=256, H=8)
#define NN 4096
#define DD 256
#define HH 8
#define DH 32
#define WPR 64  // 64-bit words per mask row: 4096/64

// ---------------- scratch (device globals; no allocation allowed) ----------
__device__ float g_Q[NN * DD];
__device__ float g_K[NN * DD];
__device__ float g_V[NN * DD];
__device__ float g_attn[NN * DD];
__device__ float g_proj[NN * DD];
__device__ unsigned long long g_mask[NN * WPR];

// ---------------- mask kernels ---------------------------------------------
__global__ void zero_mask_kernel() {
    int t = blockIdx.x * blockDim.x + threadIdx.x;
    if (t < NN * WPR) g_mask[t] = 0ULL;
}

__global__ void build_mask_kernel(const int* __restrict__ ei, int E) {
    int t = blockIdx.x * blockDim.x + threadIdx.x;
    if (t < NN) {
        // diagonal: node attends to itself
        atomicOr(&g_mask[(size_t)t * WPR + (t >> 6)], 1ULL << (t & 63));
    }
    if (t < E) {
        int s = ei[t];        // src
        int d = ei[E + t];    // dst
        atomicOr(&g_mask[(size_t)d * WPR + (s >> 6)], 1ULL << (s & 63));
    }
}

// ---------------- tiled fp32 GEMM: C[M,256] = A[M,256] @ B^T (B is [256,256] row-major)
// BM=BN=64, BK=16, 256 threads, 4x4 per thread. All dims exact multiples.
__device__ __forceinline__ void gemm_tile_nt(const float* __restrict__ A,
                                             const float* __restrict__ B,
                                             float* __restrict__ C) {
    __shared__ float Ast[16][64];
    __shared__ float Bst[16][64];

    const int tid = threadIdx.x;
    const int tx = tid & 15;        // 0..15 -> col group
    const int ty = tid >> 4;        // 0..15 -> row group
    const int row0 = blockIdx.y * 64;
    const int col0 = blockIdx.x * 64;

    const int r = tid >> 2;          // 0..63
    const int c = (tid & 3) << 2;    // 0,4,8,12

    float acc[4][4];
#pragma unroll
    for (int i = 0; i < 4; i++)
#pragma unroll
        for (int j = 0; j < 4; j++) acc[i][j] = 0.0f;

    for (int k0 = 0; k0 < 256; k0 += 16) {
        float4 av = *(const float4*)(A + (size_t)(row0 + r) * 256 + k0 + c);
        float4 bv = *(const float4*)(B + (size_t)(col0 + r) * 256 + k0 + c);
        Ast[c + 0][r] = av.x; Ast[c + 1][r] = av.y;
        Ast[c + 2][r] = av.z; Ast[c + 3][r] = av.w;
        Bst[c + 0][r] = bv.x; Bst[c + 1][r] = bv.y;
        Bst[c + 2][r] = bv.z; Bst[c + 3][r] = bv.w;
        __syncthreads();
#pragma unroll
        for (int kk = 0; kk < 16; kk++) {
            float4 a = *(const float4*)&Ast[kk][ty * 4];
            float4 b = *(const float4*)&Bst[kk][tx * 4];
            float ar[4] = {a.x, a.y, a.z, a.w};
            float br[4] = {b.x, b.y, b.z, b.w};
#pragma unroll
            for (int i = 0; i < 4; i++)
#pragma unroll
                for (int j = 0; j < 4; j++) acc[i][j] = fmaf(ar[i], br[j], acc[i][j]);
        }
        __syncthreads();
    }

#pragma unroll
    for (int i = 0; i < 4; i++) {
        float4 o = make_float4(acc[i][0], acc[i][1], acc[i][2], acc[i][3]);
        *(float4*)(C + (size_t)(row0 + ty * 4 + i) * 256 + col0 + tx * 4) = o;
    }
}

__global__ void __launch_bounds__(256) gemm_qkv_kernel(const float* __restrict__ x,
                                                       const float* __restrict__ Wq,
                                                       const float* __restrict__ Wk,
                                                       const float* __restrict__ Wv) {
    const float* B;
    float* C;
    if (blockIdx.z == 0)      { B = Wq; C = g_Q; }
    else if (blockIdx.z == 1) { B = Wk; C = g_K; }
    else                      { B = Wv; C = g_V; }
    gemm_tile_nt(x, B, C);
}

__global__ void __launch_bounds__(256) gemm_out_kernel(const float* __restrict__ Wo) {
    gemm_tile_nt(g_attn, Wo, g_proj);
}

// ---------------- sparse masked attention ----------------------------------
// One block per destination node. 8 warps = 8 heads. Online softmax over the
// (deterministic, sorted) neighbor list extracted from the bitmask row.
__global__ void __launch_bounds__(256) attn_kernel() {
    const int n = blockIdx.x;
    const int tid = threadIdx.x;
    const int h = tid >> 5;
    const int lane = tid & 31;

    __shared__ float q_s[DD];
    __shared__ unsigned short nb[NN];   // neighbor indices (worst case = N)
    __shared__ int pc[WPR];
    __shared__ int offs[WPR];
    __shared__ int cnt;

    q_s[tid] = g_Q[(size_t)n * DD + tid];

    if (tid < WPR) pc[tid] = __popcll(g_mask[(size_t)n * WPR + tid]);
    __syncthreads();
    if (tid == 0) {
        int s = 0;
        for (int w = 0; w < WPR; w++) { offs[w] = s; s += pc[w]; }
        cnt = s;
    }
    __syncthreads();
    if (tid < WPR) {
        unsigned long long word = g_mask[(size_t)n * WPR + tid];
        int o = offs[tid];
        while (word) {
            int b = __ffsll((long long)word) - 1;
            word &= word - 1;
            nb[o++] = (unsigned short)(tid * 64 + b);
        }
    }
    __syncthreads();

    const int m = cnt;  // >= 1 always (diagonal)
    const float inv_scale = 0.17677669529663688f;  // 1/sqrt(32)
    const float qd = q_s[h * DH + lane];

    float M = -INFINITY, S = 0.0f, acc = 0.0f;
    for (int i = 0; i < m; i++) {
        const int j = nb[i];
        const size_t base = (size_t)j * DD + h * DH + lane;
        float partial = qd * g_K[base];
#pragma unroll
        for (int o = 16; o > 0; o >>= 1)
            partial += __shfl_xor_sync(0xffffffffu, partial, o);
        const float s = partial * inv_scale;
        const float v = g_V[base];
        const float newM = fmaxf(M, s);
        const float corr = __expf(M - newM);   // 0 on first iter (M=-inf)
        const float p = __expf(s - newM);
        S = S * corr + p;
        acc = acc * corr + p * v;
        M = newM;
    }
    g_attn[(size_t)n * DD + h * DH + lane] = acc / S;
}

// ---------------- residual + bias + LayerNorm ------------------------------
__global__ void __launch_bounds__(256) ln_kernel(const float* __restrict__ x,
                                                 const float* __restrict__ bo,
                                                 const float* __restrict__ gamma,
                                                 const float* __restrict__ beta,
                                                 float* __restrict__ out) {
    const int n = blockIdx.x;
    const int t = threadIdx.x;
    __shared__ float red[256];
    __shared__ float red2[256];

    const float hv = x[(size_t)n * DD + t] + g_proj[(size_t)n * DD + t] + bo[t];

    red[t] = hv;
    red2[t] = hv * hv;
    __syncthreads();
#pragma unroll
    for (int s = 128; s > 0; s >>= 1) {
        if (t < s) { red[t] += red[t + s]; red2[t] += red2[t + s]; }
        __syncthreads();
    }
    const float mu = red[0] * (1.0f / DD);
    const float var = red2[0] * (1.0f / DD) - mu * mu;
    const float rstd = rsqrtf(var + 1e-5f);
    out[(size_t)n * DD + t] = (hv - mu) * rstd * gamma[t] + beta[t];
}

// ---------------- launcher --------------------------------------------------
extern "C" void kernel_launch(void* const* d_in, const int* in_sizes, int n_in,
                              void* d_out, int out_size) {
    const float* x     = (const float*)d_in[0];
    const int*   ei    = (const int*)d_in[1];
    const float* Wq    = (const float*)d_in[2];
    const float* Wk    = (const float*)d_in[3];
    const float* Wv    = (const float*)d_in[4];
    const float* Wo    = (const float*)d_in[5];
    const float* bo    = (const float*)d_in[6];
    const float* gamma = (const float*)d_in[7];
    const float* beta  = (const float*)d_in[8];
    const int E = in_sizes[1] / 2;

    zero_mask_kernel<<<(NN * WPR + 511) / 512, 512>>>();
    {
        int work = (E > NN) ? E : NN;
        build_mask_kernel<<<(work + 255) / 256, 256>>>(ei, E);
    }
    gemm_qkv_kernel<<<dim3(4, 64, 3), 256>>>(x, Wq, Wk, Wv);
    attn_kernel<<<NN, 256>>>();
    gemm_out_kernel<<<dim3(4, 64, 1), 256>>>(Wo);
    ln_kernel<<<NN, 256>>>(x, bo, gamma, beta, (float*)d_out);
}

// round 2
// speedup vs baseline: 1.0611x; 1.0611x over previous
#include <cuda_runtime.h>
#include <math.h>

// Problem constants (fixed by the reference: N=4096, D=256, H=8)
#define NN 4096
#define DD 256
#define HH 8
#define DH 32
#define WPR 64  // 64-bit words per mask row: 4096/64

// ---------------- scratch (device globals; no allocation allowed) ----------
__device__ float g_Q[NN * DD];
__device__ float g_K[NN * DD];
__device__ float g_V[NN * DD];
__device__ float g_attn[NN * DD];
__device__ float g_proj[NN * DD];
__device__ unsigned long long g_mask[NN * WPR];

// ---------------- mask kernels ---------------------------------------------
__global__ void zero_mask_kernel() {
    int t = blockIdx.x * blockDim.x + threadIdx.x;
    if (t < NN * WPR) g_mask[t] = 0ULL;
}

__global__ void build_mask_kernel(const int* __restrict__ ei, int E) {
    int t = blockIdx.x * blockDim.x + threadIdx.x;
    if (t < NN) {
        atomicOr(&g_mask[(size_t)t * WPR + (t >> 6)], 1ULL << (t & 63));
    }
    if (t < E) {
        int s = ei[t];        // src
        int d = ei[E + t];    // dst
        atomicOr(&g_mask[(size_t)d * WPR + (s >> 6)], 1ULL << (s & 63));
    }
}

// ---------------- tiled fp32 GEMM: C[M,256] = A[M,256] @ B^T ----------------
// BM=128, BN=64, BK=16, 256 threads, 8x4 outputs per thread.
__device__ __forceinline__ void gemm_tile_nt(const float* __restrict__ A,
                                             const float* __restrict__ B,
                                             float* __restrict__ C) {
    __shared__ float Ast[16][128];
    __shared__ float Bst[16][64];

    const int tid = threadIdx.x;
    const int row0 = blockIdx.y * 128;
    const int col0 = blockIdx.x * 64;

    // global-load mapping
    const int ar = tid >> 1;           // 0..127
    const int ac = (tid & 1) * 8;      // 0 or 8
    const int br = tid >> 2;           // 0..63
    const int bc = (tid & 3) * 4;      // 0,4,8,12

    // compute mapping
    const int ty = tid >> 4;           // 0..15 -> rows ty*8
    const int tx = tid & 15;           // 0..15 -> cols tx*4

    float acc[8][4];
#pragma unroll
    for (int i = 0; i < 8; i++)
#pragma unroll
        for (int j = 0; j < 4; j++) acc[i][j] = 0.0f;

    for (int k0 = 0; k0 < 256; k0 += 16) {
        float4 a0 = *(const float4*)(A + (size_t)(row0 + ar) * 256 + k0 + ac);
        float4 a1 = *(const float4*)(A + (size_t)(row0 + ar) * 256 + k0 + ac + 4);
        float4 bv = *(const float4*)(B + (size_t)(col0 + br) * 256 + k0 + bc);
        Ast[ac + 0][ar] = a0.x; Ast[ac + 1][ar] = a0.y;
        Ast[ac + 2][ar] = a0.z; Ast[ac + 3][ar] = a0.w;
        Ast[ac + 4][ar] = a1.x; Ast[ac + 5][ar] = a1.y;
        Ast[ac + 6][ar] = a1.z; Ast[ac + 7][ar] = a1.w;
        Bst[bc + 0][br] = bv.x; Bst[bc + 1][br] = bv.y;
        Bst[bc + 2][br] = bv.z; Bst[bc + 3][br] = bv.w;
        __syncthreads();
#pragma unroll
        for (int kk = 0; kk < 16; kk++) {
            float4 av0 = *(const float4*)&Ast[kk][ty * 8];
            float4 av1 = *(const float4*)&Ast[kk][ty * 8 + 4];
            float4 bvv = *(const float4*)&Bst[kk][tx * 4];
            float arr[8] = {av0.x, av0.y, av0.z, av0.w, av1.x, av1.y, av1.z, av1.w};
            float brr[4] = {bvv.x, bvv.y, bvv.z, bvv.w};
#pragma unroll
            for (int i = 0; i < 8; i++)
#pragma unroll
                for (int j = 0; j < 4; j++) acc[i][j] = fmaf(arr[i], brr[j], acc[i][j]);
        }
        __syncthreads();
    }

#pragma unroll
    for (int i = 0; i < 8; i++) {
        float4 o = make_float4(acc[i][0], acc[i][1], acc[i][2], acc[i][3]);
        *(float4*)(C + (size_t)(row0 + ty * 8 + i) * 256 + col0 + tx * 4) = o;
    }
}

__global__ void __launch_bounds__(256) gemm_qkv_kernel(const float* __restrict__ x,
                                                       const float* __restrict__ Wq,
                                                       const float* __restrict__ Wk,
                                                       const float* __restrict__ Wv) {
    const float* B;
    float* C;
    if (blockIdx.z == 0)      { B = Wq; C = g_Q; }
    else if (blockIdx.z == 1) { B = Wk; C = g_K; }
    else                      { B = Wv; C = g_V; }
    gemm_tile_nt(x, B, C);
}

__global__ void __launch_bounds__(256) gemm_out_kernel(const float* __restrict__ Wo) {
    gemm_tile_nt(g_attn, Wo, g_proj);
}

// ---------------- sparse masked attention ----------------------------------
// One block per destination node. 8 warps = 8 heads. 8-way interleaved
// neighbor processing with batched online softmax (scores stay in registers
// after the butterfly — every lane holds all 8 scores of the group).
__global__ void __launch_bounds__(256) attn_kernel() {
    const int n = blockIdx.x;
    const int tid = threadIdx.x;
    const int h = tid >> 5;
    const int lane = tid & 31;

    __shared__ unsigned short nb[NN];
    __shared__ int cnt_sm;

    // -- neighbor extraction: single-warp shuffle scan over 64 mask words --
    if (tid < 32) {
        unsigned long long w0 = g_mask[(size_t)n * WPR + 2 * tid];
        unsigned long long w1 = g_mask[(size_t)n * WPR + 2 * tid + 1];
        int c0 = __popcll(w0);
        int c1 = __popcll(w1);
        int c = c0 + c1;
        int sc = c;
#pragma unroll
        for (int o = 1; o < 32; o <<= 1) {
            int t = __shfl_up_sync(0xffffffffu, sc, o);
            if (lane >= o) sc += t;
        }
        int off = sc - c;  // exclusive prefix
        // extract bits of word 2*tid at off, word 2*tid+1 at off+c0
        int base0 = 2 * tid * 64;
        while (w0) {
            int b = __ffsll((long long)w0) - 1;
            w0 &= w0 - 1;
            nb[off++] = (unsigned short)(base0 + b);
        }
        int base1 = base0 + 64;
        off = sc - c1;
        while (w1) {
            int b = __ffsll((long long)w1) - 1;
            w1 &= w1 - 1;
            nb[off++] = (unsigned short)(base1 + b);
        }
        if (tid == 31) cnt_sm = sc;
    }
    __syncthreads();

    const int m = cnt_sm;  // >= 1 always (diagonal)
    const float inv_scale = 0.17677669529663688f;  // 1/sqrt(32)
    const int hoff = h * DH + lane;
    const float qd = g_Q[(size_t)n * DD + hoff];

    float M = -INFINITY, S = 0.0f, acc = 0.0f;

    for (int i0 = 0; i0 < m; i0 += 8) {
        float kv[8], vv[8];
        bool val[8];
#pragma unroll
        for (int t = 0; t < 8; t++) {
            int idx = i0 + t;
            val[t] = (idx < m);
            int j = val[t] ? (int)nb[idx] : (int)nb[0];
            const size_t base = (size_t)j * DD + hoff;
            kv[t] = g_K[base];
            vv[t] = g_V[base];
        }
        float p[8];
#pragma unroll
        for (int t = 0; t < 8; t++) p[t] = qd * kv[t];
        // interleaved butterfly: 8 independent reductions share the latency wall
#pragma unroll
        for (int o = 16; o > 0; o >>= 1) {
#pragma unroll
            for (int t = 0; t < 8; t++)
                p[t] += __shfl_xor_sync(0xffffffffu, p[t], o);
        }
        float s[8];
#pragma unroll
        for (int t = 0; t < 8; t++)
            s[t] = val[t] ? p[t] * inv_scale : -INFINITY;

        float gm = s[0];
#pragma unroll
        for (int t = 1; t < 8; t++) gm = fmaxf(gm, s[t]);
        const float newM = fmaxf(M, gm);
        const float corr = __expf(M - newM);  // 0 on first group
        S *= corr;
        acc *= corr;
#pragma unroll
        for (int t = 0; t < 8; t++) {
            const float e = __expf(s[t] - newM);  // 0 for invalid slots
            S += e;
            acc = fmaf(e, vv[t], acc);
        }
        M = newM;
    }
    g_attn[(size_t)n * DD + hoff] = acc / S;
}

// ---------------- residual + bias + LayerNorm ------------------------------
__global__ void __launch_bounds__(256) ln_kernel(const float* __restrict__ x,
                                                 const float* __restrict__ bo,
                                                 const float* __restrict__ gamma,
                                                 const float* __restrict__ beta,
                                                 float* __restrict__ out) {
    const int n = blockIdx.x;
    const int t = threadIdx.x;
    __shared__ float red[256];
    __shared__ float red2[256];

    const float hv = x[(size_t)n * DD + t] + g_proj[(size_t)n * DD + t] + bo[t];

    red[t] = hv;
    red2[t] = hv * hv;
    __syncthreads();
#pragma unroll
    for (int s = 128; s > 0; s >>= 1) {
        if (t < s) { red[t] += red[t + s]; red2[t] += red2[t + s]; }
        __syncthreads();
    }
    const float mu = red[0] * (1.0f / DD);
    const float var = red2[0] * (1.0f / DD) - mu * mu;
    const float rstd = rsqrtf(var + 1e-5f);
    out[(size_t)n * DD + t] = (hv - mu) * rstd * gamma[t] + beta[t];
}

// ---------------- launcher --------------------------------------------------
extern "C" void kernel_launch(void* const* d_in, const int* in_sizes, int n_in,
                              void* d_out, int out_size) {
    const float* x     = (const float*)d_in[0];
    const int*   ei    = (const int*)d_in[1];
    const float* Wq    = (const float*)d_in[2];
    const float* Wk    = (const float*)d_in[3];
    const float* Wv    = (const float*)d_in[4];
    const float* Wo    = (const float*)d_in[5];
    const float* bo    = (const float*)d_in[6];
    const float* gamma = (const float*)d_in[7];
    const float* beta  = (const float*)d_in[8];
    const int E = in_sizes[1] / 2;

    zero_mask_kernel<<<(NN * WPR + 511) / 512, 512>>>();
    {
        int work = (E > NN) ? E : NN;
        build_mask_kernel<<<(work + 255) / 256, 256>>>(ei, E);
    }
    gemm_qkv_kernel<<<dim3(4, 32, 3), 256>>>(x, Wq, Wk, Wv);
    attn_kernel<<<NN, 256>>>();
    gemm_out_kernel<<<dim3(4, 32, 1), 256>>>(Wo);
    ln_kernel<<<NN, 256>>>(x, bo, gamma, beta, (float*)d_out);
}